// round 8
// baseline (speedup 1.0000x reference)
#include <cuda_runtime.h>
#include <cuda_bf16.h>
#include <math.h>

// ---------------- problem constants ----------------
#define Bn    2
#define CIN   256
#define COUT  128
#define CTOT  384          // CIN + COUT
#define HS    64
#define WS    64
#define DS    16
#define HWD   (HS*WS*DS)   // 65536 per (b,c)
#define NWIN  1024         // 8*8*16 windows per batch
#define TTOK  64           // tokens per window
#define NI    80
#define NK    144          // NI + TTOK
#define HEADS 4
#define HD    32
#define NTOK  (Bn*NWIN*TTOK)   // 131072 tokens

// ---------------- global scratch (aliased lifetimes) ----------------
__device__ float    g_bufA[(size_t)NTOK*384];      // XC concat -> QKV
__device__ float    g_bufB[(size_t)NTOK*COUT];     // TN -> O
__device__ float    g_RES [(size_t)NTOK*COUT];     // residual tokens (conv out)
__device__ float    g_na[CTOT], g_nb[CTOT];        // fused norm scale/shift
__device__ unsigned g_wp2[(size_t)CTOT*9*COUT];    // conv weights tf32 bits: [ci][tap][co]
__device__ float    g_QKVI[Bn*NI*384];             // instruction qkv

#define g_XC  g_bufA
#define g_QKV g_bufA
#define g_TN  g_bufB
#define g_O   g_bufB

__device__ __forceinline__ unsigned f2tf32(float f) {
    unsigned u;
    asm("cvt.rna.tf32.f32 %0, %1;" : "=r"(u) : "f"(f));
    return u;
}

// ================= K0: transpose conv weights -> [ci][tap][co], tf32-rounded =================
__global__ void k_repack(const float* __restrict__ cw) {
    int i = blockIdx.x * blockDim.x + threadIdx.x;   // over CTOT*9*COUT = 442368
    if (i < CTOT*9*COUT) {
        int co  = i & 127;
        int tap = (i >> 7) % 9;
        int ci  = i / (9*128);
        g_wp2[i] = f2tf32(cw[((size_t)co*CTOT + ci)*9 + tap]);
    }
}

// ================= K1: trilinear upsample + concat -> g_XC =================
__global__ void k_build_xc(const float* __restrict__ x, const float* __restrict__ xsk) {
    int h = blockIdx.x, c = blockIdx.y, b = blockIdx.z;
    int tid = threadIdx.x;
    int w = tid >> 2, d4 = tid & 3;
    float4 v;
    if (c >= CIN) {
        v = *(const float4*)&xsk[((size_t)((b*COUT + (c-CIN))*HS + h))*1024 + w*16 + d4*4];
    } else {
        int h0 = (2*h - 1) >> 2;  float fh = (h*0.5f - 0.25f) - (float)h0;
        int w0 = (2*w - 1) >> 2;  float fw = (w*0.5f - 0.25f) - (float)w0;
        int h0c = h0 < 0 ? 0 : h0;      int h1c = (h0+1) > 31 ? 31 : (h0+1);
        int w0c = w0 < 0 ? 0 : w0;      int w1c = (w0+1) > 31 ? 31 : (w0+1);
        const float* base = &x[((size_t)(b*CIN + c)) * 16384];   // 32*32*16
        float4 v00 = *(const float4*)&base[h0c*512 + w0c*16 + d4*4];
        float4 v01 = *(const float4*)&base[h0c*512 + w1c*16 + d4*4];
        float4 v10 = *(const float4*)&base[h1c*512 + w0c*16 + d4*4];
        float4 v11 = *(const float4*)&base[h1c*512 + w1c*16 + d4*4];
        float a00 = (1.f-fh)*(1.f-fw), a01 = (1.f-fh)*fw, a10 = fh*(1.f-fw), a11 = fh*fw;
        v.x = a00*v00.x + a01*v01.x + a10*v10.x + a11*v11.x;
        v.y = a00*v00.y + a01*v01.y + a10*v10.y + a11*v11.y;
        v.z = a00*v00.z + a01*v01.z + a10*v10.z + a11*v11.z;
        v.w = a00*v00.w + a01*v01.w + a10*v10.w + a11*v11.w;
    }
    *(float4*)&g_XC[((size_t)(b*CTOT + c))*HWD + h*1024 + w*16 + d4*4] = v;
}

// ================= K2: per-channel mean/var -> fused scale/shift =================
__global__ void k_stats(const float* __restrict__ ng, const float* __restrict__ nbeta) {
    int c = blockIdx.x, tid = threadIdx.x;
    float s = 0.f, q = 0.f;
    for (int b = 0; b < Bn; b++) {
        const float* base = &g_XC[(size_t)(b*CTOT + c)*HWD];
        for (int i = tid*4; i < HWD; i += 1024) {
            float4 v = *(const float4*)&base[i];
            s += v.x + v.y + v.z + v.w;
            q += v.x*v.x + v.y*v.y + v.z*v.z + v.w*v.w;
        }
    }
    #pragma unroll
    for (int off = 16; off; off >>= 1) {
        s += __shfl_xor_sync(0xffffffffu, s, off);
        q += __shfl_xor_sync(0xffffffffu, q, off);
    }
    __shared__ float ss[8], qs[8];
    int lane = tid & 31, wid = tid >> 5;
    if (lane == 0) { ss[wid] = s; qs[wid] = q; }
    __syncthreads();
    if (tid == 0) {
        float S = 0.f, Q = 0.f;
        #pragma unroll
        for (int i = 0; i < 8; i++) { S += ss[i]; Q += qs[i]; }
        float inv = 1.f / (float)(Bn*HWD);
        float mean = S * inv;
        float var  = Q * inv - mean*mean;
        float a = ng[c] * rsqrtf(var + 1e-5f);
        g_na[c] = a;
        g_nb[c] = nbeta[c] - mean * a;
    }
}

// ================= K3: conv 3x3x1 as implicit GEMM on tensor cores (tf32 mma.sync) ============
// grid (8, 64, Bn): block = (h, 8 w-sites, 16 d) -> C[128 co][128 sites], K = 384ci*9tap.
// 8 warps: mw = wid>>2 (co half), nw = wid&3 (site quarter). Warp tile 64co x 32 sites.
// site col = sw*16 + sd.
#define CIC 16
__global__ void __launch_bounds__(256) k_conv(const float* __restrict__ cb,
                                              const float* __restrict__ lg,
                                              const float* __restrict__ lb) {
    __shared__ unsigned s_in[CIC*488];   // [ci][kh*160 + w*16 + d], ci-stride 488 (pad)
    __shared__ unsigned s_w [CIC*136];   // [ci][co], ci-stride 136 (pad)
    __shared__ float s_red[2][128], q_red[2][128];
    __shared__ float mu_s[128], rs_s[128];

    int w0 = blockIdx.x * 8, h = blockIdx.y, b = blockIdx.z;
    int tid = threadIdx.x, wid = tid >> 5, lane = tid & 31;
    int mw = wid >> 2, nw = wid & 3;
    int cow = mw * 64;
    int lg4 = lane >> 2, lm4 = lane & 3;

    float c[4][4][4];
    #pragma unroll
    for (int mi = 0; mi < 4; mi++)
        #pragma unroll
        for (int nt = 0; nt < 4; nt++)
            #pragma unroll
            for (int r = 0; r < 4; r++) c[mi][nt][r] = 0.f;

    for (int chunk = 0; chunk < CTOT/CIC; chunk++) {
        int c0 = chunk * CIC;
        __syncthreads();
        // ---- stage input halo (+ BN + leakyReLU + tf32 cvt): 16ci x 3kh x 10w x 16d ----
        for (int i = tid; i < CIC*120; i += 256) {       // float4 granularity over d
            int ci = i / 120, r = i % 120;
            int kh = r / 40, r2 = r % 40;
            int wp = r2 >> 2, d4 = r2 & 3;
            int hh = h + kh - 1, ww = w0 - 1 + wp;
            float4 v = make_float4(0.f, 0.f, 0.f, 0.f);
            if ((unsigned)hh < 64u && (unsigned)ww < 64u) {
                int cc = c0 + ci;
                float4 raw = *(const float4*)&g_XC[((size_t)(b*CTOT + cc))*HWD + hh*1024 + ww*16 + d4*4];
                float a = g_na[cc], bb = g_nb[cc];
                v.x = fmaf(a, raw.x, bb); v.y = fmaf(a, raw.y, bb);
                v.z = fmaf(a, raw.z, bb); v.w = fmaf(a, raw.w, bb);
                v.x = v.x >= 0.f ? v.x : 0.01f*v.x;
                v.y = v.y >= 0.f ? v.y : 0.01f*v.y;
                v.z = v.z >= 0.f ? v.z : 0.01f*v.z;
                v.w = v.w >= 0.f ? v.w : 0.01f*v.w;
            }
            unsigned* dst = &s_in[ci*488 + kh*160 + wp*16 + d4*4];
            dst[0] = f2tf32(v.x); dst[1] = f2tf32(v.y);
            dst[2] = f2tf32(v.z); dst[3] = f2tf32(v.w);
        }
        __syncthreads();

        for (int tap = 0; tap < 9; tap++) {
            int kh_t = tap / 3, kw_t = tap - kh_t*3;
            // ---- stage weight tile [16ci][128co] for this tap ----
            for (int i = tid; i < 512; i += 256) {       // uint4 granularity
                int ci = i >> 5, co4 = i & 31;
                uint4 wv = *(const uint4*)&g_wp2[((size_t)(c0+ci)*9 + tap)*128 + co4*4];
                *(uint4*)&s_w[ci*136 + co4*4] = wv;
            }
            __syncthreads();

            #pragma unroll
            for (int k0 = 0; k0 < 16; k0 += 8) {
                int kc = k0 + lm4;
                unsigned a[4][4];
                #pragma unroll
                for (int mi = 0; mi < 4; mi++) {
                    int rb = cow + mi*16 + lg4;
                    a[mi][0] = s_w[kc*136 + rb];
                    a[mi][1] = s_w[kc*136 + rb + 8];
                    a[mi][2] = s_w[(kc+4)*136 + rb];
                    a[mi][3] = s_w[(kc+4)*136 + rb + 8];
                }
                unsigned bf[4][2];
                #pragma unroll
                for (int nt = 0; nt < 4; nt++) {
                    int swt = nw*2 + (nt >> 1);
                    int sdb = (nt & 1) * 8;
                    int base = kc*488 + kh_t*160 + (swt + kw_t)*16 + sdb + lg4;
                    bf[nt][0] = s_in[base];
                    bf[nt][1] = s_in[base + 4*488];
                }
                #pragma unroll
                for (int mi = 0; mi < 4; mi++)
                    #pragma unroll
                    for (int nt = 0; nt < 4; nt++) {
                        asm("mma.sync.aligned.m16n8k8.row.col.f32.tf32.tf32.f32 "
                            "{%0,%1,%2,%3}, {%4,%5,%6,%7}, {%8,%9}, {%0,%1,%2,%3};"
                            : "+f"(c[mi][nt][0]), "+f"(c[mi][nt][1]),
                              "+f"(c[mi][nt][2]), "+f"(c[mi][nt][3])
                            : "r"(a[mi][0]), "r"(a[mi][1]), "r"(a[mi][2]), "r"(a[mi][3]),
                              "r"(bf[nt][0]), "r"(bf[nt][1]));
                    }
            }
            __syncthreads();   // before next tap's s_w overwrite
        }
    }

    // ---- epilogue: bias, channel-LN over co (128), token-layout stores ----
    float cb0[4], cb1[4];
    #pragma unroll
    for (int mi = 0; mi < 4; mi++) {
        cb0[mi] = cb[cow + mi*16 + lg4];
        cb1[mi] = cb[cow + mi*16 + lg4 + 8];
    }
    // stats: per nt, two columns
    #pragma unroll
    for (int nt = 0; nt < 4; nt++) {
        float s0 = 0.f, q0 = 0.f, s1 = 0.f, q1 = 0.f;
        #pragma unroll
        for (int mi = 0; mi < 4; mi++) {
            float y00 = c[mi][nt][0] + cb0[mi];
            float y01 = c[mi][nt][1] + cb0[mi];
            float y10 = c[mi][nt][2] + cb1[mi];
            float y11 = c[mi][nt][3] + cb1[mi];
            s0 += y00 + y10; q0 += y00*y00 + y10*y10;
            s1 += y01 + y11; q1 += y01*y01 + y11*y11;
        }
        #pragma unroll
        for (int off = 4; off < 32; off <<= 1) {
            s0 += __shfl_xor_sync(0xffffffffu, s0, off);
            q0 += __shfl_xor_sync(0xffffffffu, q0, off);
            s1 += __shfl_xor_sync(0xffffffffu, s1, off);
            q1 += __shfl_xor_sync(0xffffffffu, q1, off);
        }
        if (lg4 == 0) {
            int swt = nw*2 + (nt >> 1);
            int col0 = swt*16 + (nt & 1)*8 + lm4*2;
            s_red[mw][col0] = s0; q_red[mw][col0] = q0;
            s_red[mw][col0+1] = s1; q_red[mw][col0+1] = q1;
        }
    }
    __syncthreads();
    if (tid < 128) {
        float s = s_red[0][tid] + s_red[1][tid];
        float q = q_red[0][tid] + q_red[1][tid];
        float m = s * (1.f/128.f);
        float var = q * (1.f/128.f) - m*m;
        mu_s[tid] = m;
        rs_s[tid] = rsqrtf(var + 1e-5f);
    }
    __syncthreads();

    int nh = h >> 3, wh = h & 7, nw8 = blockIdx.x;
    int tokw = (b*NWIN + (nh*8 + nw8)*16);      // + sd, then *64 + wh*8 + sw
    #pragma unroll
    for (int mi = 0; mi < 4; mi++) {
        int r0 = cow + mi*16 + lg4, r1 = r0 + 8;
        float lg0 = lg[r0], lb0 = lb[r0], lg1 = lg[r1], lb1 = lb[r1];
        #pragma unroll
        for (int nt = 0; nt < 4; nt++) {
            int swt = nw*2 + (nt >> 1);
            int col0 = swt*16 + (nt & 1)*8 + lm4*2;
            #pragma unroll
            for (int j = 0; j < 2; j++) {
                int col = col0 + j;
                int sw = col >> 4, sd = col & 15;
                size_t token = (size_t)(tokw + sd)*64 + wh*8 + sw;
                float mu = mu_s[col], rs = rs_s[col];
                float ya = c[mi][nt][j]     + cb0[mi];   // row r0
                float yb = c[mi][nt][j + 2] + cb1[mi];   // row r1
                g_RES[token*COUT + r0] = ya;
                g_RES[token*COUT + r1] = yb;
                g_TN [token*COUT + r0] = (ya - mu)*rs*lg0 + lb0;
                g_TN [token*COUT + r1] = (yb - mu)*rs*lg1 + lb1;
            }
        }
    }
}

// ================= K4: GEMM  C[m][n] = sum_k A[m][k]*B[n][k] + bias[n]  (K=128) =================
__global__ void __launch_bounds__(256) k_gemm(const float* __restrict__ Aext, int asel,
                                              const float* __restrict__ B,
                                              const float* __restrict__ bias,
                                              int csel, int M, int N) {
    __shared__ float As[64*68];   // transposed [k][m]
    __shared__ float Bs[64*68];   // transposed [k][n]
    const float* A = asel ? Aext : g_TN;
    float* C = csel ? g_QKVI : g_QKV;
    int m0 = blockIdx.x*64, n0 = blockIdx.y*64;
    int tid = threadIdx.x, tx = tid & 15, ty = tid >> 4;
    float acc[4][4] = {};
    for (int kc = 0; kc < 2; kc++) {
        int k0 = kc * 64;
        __syncthreads();
        for (int i = tid; i < 1024; i += 256) {
            int row = i >> 4, kq = i & 15;
            float4 v = make_float4(0.f,0.f,0.f,0.f);
            if (m0 + row < M) v = *(const float4*)&A[(size_t)(m0+row)*128 + k0 + kq*4];
            As[(kq*4+0)*68+row]=v.x; As[(kq*4+1)*68+row]=v.y; As[(kq*4+2)*68+row]=v.z; As[(kq*4+3)*68+row]=v.w;
        }
        for (int i = tid; i < 1024; i += 256) {
            int row = i >> 4, kq = i & 15;
            float4 v = *(const float4*)&B[(size_t)(n0+row)*128 + k0 + kq*4];
            Bs[(kq*4+0)*68+row]=v.x; Bs[(kq*4+1)*68+row]=v.y; Bs[(kq*4+2)*68+row]=v.z; Bs[(kq*4+3)*68+row]=v.w;
        }
        __syncthreads();
        #pragma unroll 8
        for (int k = 0; k < 64; k++) {
            float4 aq = *(const float4*)&As[k*68 + ty*4];
            float4 bq = *(const float4*)&Bs[k*68 + tx*4];
            float av[4] = {aq.x, aq.y, aq.z, aq.w};
            float bv[4] = {bq.x, bq.y, bq.z, bq.w};
            #pragma unroll
            for (int i = 0; i < 4; i++)
                #pragma unroll
                for (int j = 0; j < 4; j++)
                    acc[i][j] += av[i]*bv[j];
        }
    }
    #pragma unroll
    for (int i = 0; i < 4; i++) {
        int m = m0 + ty*4 + i;
        if (m < M) {
            #pragma unroll
            for (int j = 0; j < 4; j++) {
                int n = n0 + tx*4 + j;
                C[(size_t)m*N + n] = acc[i][j] + bias[n];
            }
        }
    }
}

// ================= K5: windowed attention with instruction keys =================
__global__ void __launch_bounds__(256) k_attn(const float* __restrict__ bias_c,
                                              const float* __restrict__ bias_i) {
    __shared__ float k_s[NK*36];     // [key][ch(32)+pad4]
    __shared__ float v_s[NK*36];
    int widx = blockIdx.x, head = blockIdx.y, b = blockIdx.z;
    int tid = threadIdx.x;
    int tokbase = (b*NWIN + widx)*TTOK;
    int qoff = head*HD, koff = 128 + head*HD, voff = 256 + head*HD;

    for (int i = tid; i < NI*32; i += 256) {
        int n = i >> 5, ch = i & 31;
        const float* r = &g_QKVI[(size_t)(b*NI + n)*384];
        k_s[n*36 + ch] = r[koff + ch];
        v_s[n*36 + ch] = r[voff + ch];
    }
    for (int i = tid; i < 64*32; i += 256) {
        int t = i >> 5, ch = i & 31;
        const float* r = &g_QKV[(size_t)(tokbase+t)*384];
        k_s[(NI+t)*36 + ch] = r[koff + ch];
        v_s[(NI+t)*36 + ch] = r[voff + ch];
    }
    __syncthreads();

    int qt = tid >> 2, kg = tid & 3;
    const float* qp = &g_QKV[(size_t)(tokbase+qt)*384 + qoff];
    float4 qr[8];
    #pragma unroll
    for (int c = 0; c < 8; c++) qr[c] = *(const float4*)&qp[c*4];

    const float scale = 0.17677669529663687f;   // 32^-0.5
    float p[36];
    float mloc = -1e30f;
    #pragma unroll 4
    for (int j = 0; j < 36; j++) {
        int kt = kg + 4*j;
        float acc = 0.f;
        #pragma unroll
        for (int c = 0; c < 8; c++) {
            float4 kv = *(const float4*)&k_s[kt*36 + c*4];
            acc += qr[c].x*kv.x + qr[c].y*kv.y + qr[c].z*kv.z + qr[c].w*kv.w;
        }
        float bv = (kt < NI) ? bias_i[(head*64 + qt)*NI + kt]
                             : bias_c[(head*64 + qt)*64 + (kt - NI)];
        p[j] = acc*scale + bv;
        mloc = fmaxf(mloc, p[j]);
    }
    mloc = fmaxf(mloc, __shfl_xor_sync(0xffffffffu, mloc, 1));
    mloc = fmaxf(mloc, __shfl_xor_sync(0xffffffffu, mloc, 2));
    float s = 0.f;
    #pragma unroll
    for (int j = 0; j < 36; j++) { p[j] = __expf(p[j] - mloc); s += p[j]; }
    s += __shfl_xor_sync(0xffffffffu, s, 1);
    s += __shfl_xor_sync(0xffffffffu, s, 2);
    float inv = 1.f / s;

    float acc[32];
    #pragma unroll
    for (int c = 0; c < 32; c++) acc[c] = 0.f;
    #pragma unroll 4
    for (int j = 0; j < 36; j++) {
        int kt = kg + 4*j;
        float pj = p[j];
        const float* vb = &v_s[kt*36];
        #pragma unroll
        for (int c = 0; c < 8; c++) {
            float4 v = *(const float4*)&vb[c*4];
            acc[c*4+0] += pj*v.x; acc[c*4+1] += pj*v.y;
            acc[c*4+2] += pj*v.z; acc[c*4+3] += pj*v.w;
        }
    }
    #pragma unroll
    for (int c = 0; c < 32; c++) {
        acc[c] += __shfl_xor_sync(0xffffffffu, acc[c], 1);
        acc[c] += __shfl_xor_sync(0xffffffffu, acc[c], 2);
    }
    float* op = &g_O[(size_t)(tokbase + qt)*COUT + head*HD + kg*8];
    *(float4*)(op    ) = make_float4(acc[kg*8+0]*inv, acc[kg*8+1]*inv, acc[kg*8+2]*inv, acc[kg*8+3]*inv);
    *(float4*)(op + 4) = make_float4(acc[kg*8+4]*inv, acc[kg*8+5]*inv, acc[kg*8+6]*inv, acc[kg*8+7]*inv);
}

// ================= K6: proj + residual + un-window -> output (B,C,H,W,D) =================
__global__ void __launch_bounds__(256) k_proj(const float* __restrict__ pw,
                                              const float* __restrict__ pb,
                                              float* __restrict__ out) {
    __shared__ float pw_s[64*130];  // [k][c]
    __shared__ float o_s [128*20];  // [k][d(16)+pad]
    int w = blockIdx.x, h = blockIdx.y, b = blockIdx.z;
    int tid = threadIdx.x;
    int nh = h >> 3, wh = h & 7, nw8 = w >> 3, ww = w & 7;
    int wbase = (nh*8 + nw8)*16;
    int ttok  = wh*8 + ww;
    int tok0  = (b*NWIN + wbase)*TTOK + ttok;    // token(d) = tok0 + d*64

    for (int i = tid; i < 2048; i += 256) {
        int d = i >> 7, k = i & 127;
        o_s[k*20 + d] = g_O[(size_t)(tok0 + d*TTOK)*COUT + k];
    }
    int c = tid & 127, dg = tid >> 7;
    float acc[8] = {};
    for (int kc = 0; kc < 2; kc++) {
        __syncthreads();
        for (int i = tid; i < 8192; i += 256) {
            int cc = i >> 6, kk = i & 63;
            pw_s[kk*130 + cc] = pw[(size_t)cc*128 + kc*64 + kk];
        }
        __syncthreads();
        #pragma unroll 8
        for (int k = 0; k < 64; k++) {
            float wv = pw_s[k*130 + c];
            float4 v0 = *(const float4*)&o_s[(kc*64 + k)*20 + dg*8];
            float4 v1 = *(const float4*)&o_s[(kc*64 + k)*20 + dg*8 + 4];
            acc[0]+=wv*v0.x; acc[1]+=wv*v0.y; acc[2]+=wv*v0.z; acc[3]+=wv*v0.w;
            acc[4]+=wv*v1.x; acc[5]+=wv*v1.y; acc[6]+=wv*v1.z; acc[7]+=wv*v1.w;
        }
    }
    float bias = pb[c];
    #pragma unroll
    for (int j = 0; j < 8; j++) {
        int d = dg*8 + j;
        acc[j] += g_RES[(size_t)(tok0 + d*TTOK)*COUT + c] + bias;
    }
    size_t obase = ((size_t)(b*COUT + c))*HWD + h*1024 + w*16;
    *(float4*)&out[obase + dg*8    ] = make_float4(acc[0], acc[1], acc[2], acc[3]);
    *(float4*)&out[obase + dg*8 + 4] = make_float4(acc[4], acc[5], acc[6], acc[7]);
}

// ================= launch =================
extern "C" void kernel_launch(void* const* d_in, const int* in_sizes, int n_in,
                              void* d_out, int out_size) {
    const float* x     = (const float*)d_in[0];
    const float* xsk   = (const float*)d_in[1];
    const float* xins  = (const float*)d_in[2];
    const float* ng    = (const float*)d_in[3];
    const float* nbeta = (const float*)d_in[4];
    const float* cw    = (const float*)d_in[5];
    const float* cb    = (const float*)d_in[6];
    const float* lg    = (const float*)d_in[7];
    const float* lbeta = (const float*)d_in[8];
    const float* qw    = (const float*)d_in[9];
    const float* qb    = (const float*)d_in[10];
    const float* pw    = (const float*)d_in[11];
    const float* pb    = (const float*)d_in[12];
    const float* bc    = (const float*)d_in[13];
    const float* bi    = (const float*)d_in[14];
    float* out = (float*)d_out;

    k_repack  <<<1728, 256>>>(cw);
    k_build_xc<<<dim3(HS, CTOT, Bn), 256>>>(x, xsk);
    k_stats   <<<CTOT, 256>>>(ng, nbeta);
    k_conv    <<<dim3(8, HS, Bn), 256>>>(cb, lg, lbeta);
    k_gemm    <<<dim3(NTOK/64, 6), 256>>>(nullptr, 0, qw, qb, 0, NTOK, 384);
    k_gemm    <<<dim3(3, 6), 256>>>(xins, 1, qw, qb, 1, Bn*NI, 384);
    k_attn    <<<dim3(NWIN, HEADS, Bn), 256>>>(bc, bi);
    k_proj    <<<dim3(WS, HS, Bn), 256>>>(pw, pb, out);
}

// round 9
// speedup vs baseline: 1.1078x; 1.1078x over previous
#include <cuda_runtime.h>
#include <cuda_bf16.h>
#include <math.h>

// ---------------- problem constants ----------------
#define Bn    2
#define CIN   256
#define COUT  128
#define CTOT  384          // CIN + COUT
#define HS    64
#define WS    64
#define DS    16
#define HWD   (HS*WS*DS)   // 65536 per (b,c)
#define NWIN  1024         // 8*8*16 windows per batch
#define TTOK  64           // tokens per window
#define NI    80
#define NK    144          // NI + TTOK
#define HEADS 4
#define HD    32
#define NTOK  (Bn*NWIN*TTOK)   // 131072 tokens

// ---------------- global scratch (aliased lifetimes) ----------------
__device__ float    g_bufA[(size_t)NTOK*384];      // XC concat -> QKV
__device__ float    g_bufB[(size_t)NTOK*COUT];     // TN -> O
__device__ float    g_RES [(size_t)NTOK*COUT];     // residual tokens (conv out)
__device__ float    g_na[CTOT], g_nb[CTOT];        // fused norm scale/shift
__device__ unsigned g_wp2[(size_t)CTOT*9*COUT];    // conv weights tf32 bits: [ci][tap][co]
__device__ unsigned g_qw32[(size_t)128*384];       // qkv weights tf32 bits: [k][n]
__device__ float    g_QKVI[Bn*NI*384];             // instruction qkv

#define g_XC  g_bufA
#define g_QKV g_bufA
#define g_TN  g_bufB
#define g_O   g_bufB

__device__ __forceinline__ unsigned f2tf32(float f) {
    unsigned u;
    asm("cvt.rna.tf32.f32 %0, %1;" : "=r"(u) : "f"(f));
    return u;
}

// ================= K0a: transpose conv weights -> [ci][tap][co], tf32-rounded =================
__global__ void k_repack(const float* __restrict__ cw) {
    int i = blockIdx.x * blockDim.x + threadIdx.x;   // over CTOT*9*COUT = 442368
    if (i < CTOT*9*COUT) {
        int co  = i & 127;
        int tap = (i >> 7) % 9;
        int ci  = i / (9*128);
        g_wp2[i] = f2tf32(cw[((size_t)co*CTOT + ci)*9 + tap]);
    }
}

// ================= K0b: qkv weights [n][k] -> tf32 [k][n] =================
__global__ void k_repack_qw(const float* __restrict__ qw) {
    int i = blockIdx.x * blockDim.x + threadIdx.x;   // over 128*384 = 49152
    if (i < 128*384) {
        int n = i % 384, k = i / 384;
        g_qw32[i] = f2tf32(qw[(size_t)n*128 + k]);
    }
}

// ================= K1: trilinear upsample + concat -> g_XC =================
__global__ void k_build_xc(const float* __restrict__ x, const float* __restrict__ xsk) {
    int h = blockIdx.x, c = blockIdx.y, b = blockIdx.z;
    int tid = threadIdx.x;
    int w = tid >> 2, d4 = tid & 3;
    float4 v;
    if (c >= CIN) {
        v = *(const float4*)&xsk[((size_t)((b*COUT + (c-CIN))*HS + h))*1024 + w*16 + d4*4];
    } else {
        int h0 = (2*h - 1) >> 2;  float fh = (h*0.5f - 0.25f) - (float)h0;
        int w0 = (2*w - 1) >> 2;  float fw = (w*0.5f - 0.25f) - (float)w0;
        int h0c = h0 < 0 ? 0 : h0;      int h1c = (h0+1) > 31 ? 31 : (h0+1);
        int w0c = w0 < 0 ? 0 : w0;      int w1c = (w0+1) > 31 ? 31 : (w0+1);
        const float* base = &x[((size_t)(b*CIN + c)) * 16384];   // 32*32*16
        float4 v00 = *(const float4*)&base[h0c*512 + w0c*16 + d4*4];
        float4 v01 = *(const float4*)&base[h0c*512 + w1c*16 + d4*4];
        float4 v10 = *(const float4*)&base[h1c*512 + w0c*16 + d4*4];
        float4 v11 = *(const float4*)&base[h1c*512 + w1c*16 + d4*4];
        float a00 = (1.f-fh)*(1.f-fw), a01 = (1.f-fh)*fw, a10 = fh*(1.f-fw), a11 = fh*fw;
        v.x = a00*v00.x + a01*v01.x + a10*v10.x + a11*v11.x;
        v.y = a00*v00.y + a01*v01.y + a10*v10.y + a11*v11.y;
        v.z = a00*v00.z + a01*v01.z + a10*v10.z + a11*v11.z;
        v.w = a00*v00.w + a01*v01.w + a10*v10.w + a11*v11.w;
    }
    *(float4*)&g_XC[((size_t)(b*CTOT + c))*HWD + h*1024 + w*16 + d4*4] = v;
}

// ================= K2: per-channel mean/var -> fused scale/shift =================
__global__ void k_stats(const float* __restrict__ ng, const float* __restrict__ nbeta) {
    int c = blockIdx.x, tid = threadIdx.x;
    float s = 0.f, q = 0.f;
    for (int b = 0; b < Bn; b++) {
        const float* base = &g_XC[(size_t)(b*CTOT + c)*HWD];
        for (int i = tid*4; i < HWD; i += 1024) {
            float4 v = *(const float4*)&base[i];
            s += v.x + v.y + v.z + v.w;
            q += v.x*v.x + v.y*v.y + v.z*v.z + v.w*v.w;
        }
    }
    #pragma unroll
    for (int off = 16; off; off >>= 1) {
        s += __shfl_xor_sync(0xffffffffu, s, off);
        q += __shfl_xor_sync(0xffffffffu, q, off);
    }
    __shared__ float ss[8], qs[8];
    int lane = tid & 31, wid = tid >> 5;
    if (lane == 0) { ss[wid] = s; qs[wid] = q; }
    __syncthreads();
    if (tid == 0) {
        float S = 0.f, Q = 0.f;
        #pragma unroll
        for (int i = 0; i < 8; i++) { S += ss[i]; Q += qs[i]; }
        float inv = 1.f / (float)(Bn*HWD);
        float mean = S * inv;
        float var  = Q * inv - mean*mean;
        float a = ng[c] * rsqrtf(var + 1e-5f);
        g_na[c] = a;
        g_nb[c] = nbeta[c] - mean * a;
    }
}

// ================= K3: conv 3x3x1 implicit GEMM (tf32 mma), ping-pong weight tiles ===========
// grid (8, 64, Bn): block = (h, 8 w-sites, 16 d) -> C[128 co][128 sites], K = 384ci*9tap.
#define CIC 16
__global__ void __launch_bounds__(256) k_conv(const float* __restrict__ cb,
                                              const float* __restrict__ lg,
                                              const float* __restrict__ lb) {
    __shared__ unsigned s_in[CIC*488];     // [ci][kh*160 + w*16 + d]   31232B
    __shared__ unsigned s_w[2][CIC*136];   // ping-pong [ci][co]        17408B
    // LN reduction scratch aliases s_in (dead after mainloop)
    float* s_red = (float*)s_in;           // [2][128]
    float* q_red = s_red + 256;            // [2][128]
    float* mu_s  = q_red + 256;            // [128]
    float* rs_s  = mu_s + 128;             // [128]

    int w0 = blockIdx.x * 8, h = blockIdx.y, b = blockIdx.z;
    int tid = threadIdx.x, wid = tid >> 5, lane = tid & 31;
    int mw = wid >> 2, nw = wid & 3;
    int cow = mw * 64;
    int lg4 = lane >> 2, lm4 = lane & 3;

    float c[4][4][4];
    #pragma unroll
    for (int mi = 0; mi < 4; mi++)
        #pragma unroll
        for (int nt = 0; nt < 4; nt++)
            #pragma unroll
            for (int r = 0; r < 4; r++) c[mi][nt][r] = 0.f;

    const int NCHUNK = CTOT/CIC;
    for (int chunk = 0; chunk < NCHUNK; chunk++) {
        int c0 = chunk * CIC;
        // ---- stage input halo (+ BN + leakyReLU + tf32): 16ci x 3kh x 10w x 16d ----
        for (int i = tid; i < CIC*120; i += 256) {
            int ci = i / 120, r = i % 120;
            int kh = r / 40, r2 = r % 40;
            int wp = r2 >> 2, d4 = r2 & 3;
            int hh = h + kh - 1, ww = w0 - 1 + wp;
            float4 v = make_float4(0.f, 0.f, 0.f, 0.f);
            if ((unsigned)hh < 64u && (unsigned)ww < 64u) {
                int cc = c0 + ci;
                float4 raw = *(const float4*)&g_XC[((size_t)(b*CTOT + cc))*HWD + hh*1024 + ww*16 + d4*4];
                float a = g_na[cc], bb = g_nb[cc];
                v.x = fmaf(a, raw.x, bb); v.y = fmaf(a, raw.y, bb);
                v.z = fmaf(a, raw.z, bb); v.w = fmaf(a, raw.w, bb);
                v.x = v.x >= 0.f ? v.x : 0.01f*v.x;
                v.y = v.y >= 0.f ? v.y : 0.01f*v.y;
                v.z = v.z >= 0.f ? v.z : 0.01f*v.z;
                v.w = v.w >= 0.f ? v.w : 0.01f*v.w;
            }
            unsigned* dst = &s_in[ci*488 + kh*160 + wp*16 + d4*4];
            dst[0] = f2tf32(v.x); dst[1] = f2tf32(v.y);
            dst[2] = f2tf32(v.z); dst[3] = f2tf32(v.w);
        }
        if (chunk == 0) {
            // prime first weight tile (chunk0, tap0) into buffer 0
            for (int i = tid; i < 512; i += 256) {
                int ci = i >> 5, co4 = i & 31;
                uint4 wv = *(const uint4*)&g_wp2[((size_t)ci*9 + 0)*128 + co4*4];
                *(uint4*)&s_w[0][ci*136 + co4*4] = wv;
            }
        }
        __syncthreads();

        for (int tap = 0; tap < 9; tap++) {
            int cur = (chunk*9 + tap) & 1;
            int kh_t = tap / 3, kw_t = tap - kh_t*3;
            // ---- stage NEXT weight tile into the other buffer (overlaps mma) ----
            {
                int ntap = tap + 1, nchunk = chunk;
                if (ntap == 9) { ntap = 0; nchunk++; }
                if (nchunk < NCHUNK) {
                    int nc0 = nchunk * CIC;
                    for (int i = tid; i < 512; i += 256) {
                        int ci = i >> 5, co4 = i & 31;
                        uint4 wv = *(const uint4*)&g_wp2[((size_t)(nc0+ci)*9 + ntap)*128 + co4*4];
                        *(uint4*)&s_w[cur^1][ci*136 + co4*4] = wv;
                    }
                }
            }
            // ---- mma from current buffer ----
            #pragma unroll
            for (int k0 = 0; k0 < 16; k0 += 8) {
                int kc = k0 + lm4;
                unsigned a[4][4];
                #pragma unroll
                for (int mi = 0; mi < 4; mi++) {
                    int rb = cow + mi*16 + lg4;
                    a[mi][0] = s_w[cur][kc*136 + rb];
                    a[mi][1] = s_w[cur][kc*136 + rb + 8];
                    a[mi][2] = s_w[cur][(kc+4)*136 + rb];
                    a[mi][3] = s_w[cur][(kc+4)*136 + rb + 8];
                }
                unsigned bf[4][2];
                #pragma unroll
                for (int nt = 0; nt < 4; nt++) {
                    int swt = nw*2 + (nt >> 1);
                    int sdb = (nt & 1) * 8;
                    int base = kc*488 + kh_t*160 + (swt + kw_t)*16 + sdb + lg4;
                    bf[nt][0] = s_in[base];
                    bf[nt][1] = s_in[base + 4*488];
                }
                #pragma unroll
                for (int mi = 0; mi < 4; mi++)
                    #pragma unroll
                    for (int nt = 0; nt < 4; nt++) {
                        asm("mma.sync.aligned.m16n8k8.row.col.f32.tf32.tf32.f32 "
                            "{%0,%1,%2,%3}, {%4,%5,%6,%7}, {%8,%9}, {%0,%1,%2,%3};"
                            : "+f"(c[mi][nt][0]), "+f"(c[mi][nt][1]),
                              "+f"(c[mi][nt][2]), "+f"(c[mi][nt][3])
                            : "r"(a[mi][0]), "r"(a[mi][1]), "r"(a[mi][2]), "r"(a[mi][3]),
                              "r"(bf[nt][0]), "r"(bf[nt][1]));
                    }
            }
            __syncthreads();   // next-buffer staged + current reads done
        }
    }

    // ---- epilogue: bias, channel-LN over co (128), token-layout stores ----
    float cb0[4], cb1[4];
    #pragma unroll
    for (int mi = 0; mi < 4; mi++) {
        cb0[mi] = cb[cow + mi*16 + lg4];
        cb1[mi] = cb[cow + mi*16 + lg4 + 8];
    }
    #pragma unroll
    for (int nt = 0; nt < 4; nt++) {
        float s0 = 0.f, q0 = 0.f, s1 = 0.f, q1 = 0.f;
        #pragma unroll
        for (int mi = 0; mi < 4; mi++) {
            float y00 = c[mi][nt][0] + cb0[mi];
            float y01 = c[mi][nt][1] + cb0[mi];
            float y10 = c[mi][nt][2] + cb1[mi];
            float y11 = c[mi][nt][3] + cb1[mi];
            s0 += y00 + y10; q0 += y00*y00 + y10*y10;
            s1 += y01 + y11; q1 += y01*y01 + y11*y11;
        }
        #pragma unroll
        for (int off = 4; off < 32; off <<= 1) {
            s0 += __shfl_xor_sync(0xffffffffu, s0, off);
            q0 += __shfl_xor_sync(0xffffffffu, q0, off);
            s1 += __shfl_xor_sync(0xffffffffu, s1, off);
            q1 += __shfl_xor_sync(0xffffffffu, q1, off);
        }
        if (lg4 == 0) {
            int swt = nw*2 + (nt >> 1);
            int col0 = swt*16 + (nt & 1)*8 + lm4*2;
            s_red[mw*128 + col0] = s0; q_red[mw*128 + col0] = q0;
            s_red[mw*128 + col0+1] = s1; q_red[mw*128 + col0+1] = q1;
        }
    }
    __syncthreads();
    if (tid < 128) {
        float s = s_red[tid] + s_red[128 + tid];
        float q = q_red[tid] + q_red[128 + tid];
        float m = s * (1.f/128.f);
        float var = q * (1.f/128.f) - m*m;
        mu_s[tid] = m;
        rs_s[tid] = rsqrtf(var + 1e-5f);
    }
    __syncthreads();

    int nh = h >> 3, wh = h & 7, nw8 = blockIdx.x;
    int tokw = (b*NWIN + (nh*8 + nw8)*16);
    #pragma unroll
    for (int mi = 0; mi < 4; mi++) {
        int r0 = cow + mi*16 + lg4, r1 = r0 + 8;
        float lg0 = lg[r0], lb0 = lb[r0], lg1 = lg[r1], lb1 = lb[r1];
        #pragma unroll
        for (int nt = 0; nt < 4; nt++) {
            int swt = nw*2 + (nt >> 1);
            int col0 = swt*16 + (nt & 1)*8 + lm4*2;
            #pragma unroll
            for (int j = 0; j < 2; j++) {
                int col = col0 + j;
                int sw = col >> 4, sd = col & 15;
                size_t token = (size_t)(tokw + sd)*64 + wh*8 + sw;
                float mu = mu_s[col], rs = rs_s[col];
                float ya = c[mi][nt][j]     + cb0[mi];
                float yb = c[mi][nt][j + 2] + cb1[mi];
                g_RES[token*COUT + r0] = ya;
                g_RES[token*COUT + r1] = yb;
                g_TN [token*COUT + r0] = (ya - mu)*rs*lg0 + lb0;
                g_TN [token*COUT + r1] = (yb - mu)*rs*lg1 + lb1;
            }
        }
    }
}

// ================= K4a: QKV GEMM on tensor cores (tf32): C[NTOK][384] = TN @ W^T + bias =====
// grid (NTOK/128, 3). Block tile 128m x 128n, K=128 in 4 chunks of 32.
__global__ void __launch_bounds__(256) k_gemm_tc(const float* __restrict__ bias) {
    __shared__ unsigned sA[32*136];   // [k][m]
    __shared__ unsigned sB[32*136];   // [k][n]
    int m0 = blockIdx.x * 128, n0 = blockIdx.y * 128;
    int tid = threadIdx.x, wid = tid >> 5, lane = tid & 31;
    int mw = wid >> 2, nw = wid & 3;
    int lg4 = lane >> 2, lm4 = lane & 3;

    float c[4][4][4];
    #pragma unroll
    for (int mi = 0; mi < 4; mi++)
        #pragma unroll
        for (int nt = 0; nt < 4; nt++)
            #pragma unroll
            for (int r = 0; r < 4; r++) c[mi][nt][r] = 0.f;

    for (int kc = 0; kc < 4; kc++) {
        int k0 = kc * 32;
        __syncthreads();
        // stage A transposed [k][m]: conflict-free scalar writes (m = lane-consecutive)
        for (int i = tid; i < 1024; i += 256) {
            int m = i & 127, kq = i >> 7;
            float4 v = *(const float4*)&g_TN[(size_t)(m0+m)*128 + k0 + kq*4];
            sA[(kq*4+0)*136 + m] = f2tf32(v.x);
            sA[(kq*4+1)*136 + m] = f2tf32(v.y);
            sA[(kq*4+2)*136 + m] = f2tf32(v.z);
            sA[(kq*4+3)*136 + m] = f2tf32(v.w);
        }
        // stage B [k][n]: direct tf32 copy, uint4
        for (int i = tid; i < 1024; i += 256) {
            int n4 = i & 31, k = i >> 5;
            uint4 wv = *(const uint4*)&g_qw32[(size_t)(k0+k)*384 + n0 + n4*4];
            *(uint4*)&sB[k*136 + n4*4] = wv;
        }
        __syncthreads();
        #pragma unroll
        for (int ks = 0; ks < 4; ks++) {
            int kk = ks*8 + lm4;
            unsigned a[4][4];
            #pragma unroll
            for (int mi = 0; mi < 4; mi++) {
                int rb = mw*64 + mi*16 + lg4;
                a[mi][0] = sA[kk*136 + rb];
                a[mi][1] = sA[kk*136 + rb + 8];
                a[mi][2] = sA[(kk+4)*136 + rb];
                a[mi][3] = sA[(kk+4)*136 + rb + 8];
            }
            unsigned bf[4][2];
            #pragma unroll
            for (int nt = 0; nt < 4; nt++) {
                int cbn = nw*32 + nt*8 + lg4;
                bf[nt][0] = sB[kk*136 + cbn];
                bf[nt][1] = sB[(kk+4)*136 + cbn];
            }
            #pragma unroll
            for (int mi = 0; mi < 4; mi++)
                #pragma unroll
                for (int nt = 0; nt < 4; nt++) {
                    asm("mma.sync.aligned.m16n8k8.row.col.f32.tf32.tf32.f32 "
                        "{%0,%1,%2,%3}, {%4,%5,%6,%7}, {%8,%9}, {%0,%1,%2,%3};"
                        : "+f"(c[mi][nt][0]), "+f"(c[mi][nt][1]),
                          "+f"(c[mi][nt][2]), "+f"(c[mi][nt][3])
                        : "r"(a[mi][0]), "r"(a[mi][1]), "r"(a[mi][2]), "r"(a[mi][3]),
                          "r"(bf[nt][0]), "r"(bf[nt][1]));
                }
        }
    }
    // epilogue: bias + store
    #pragma unroll
    for (int mi = 0; mi < 4; mi++) {
        size_t row0 = (size_t)(m0 + mw*64 + mi*16 + lg4);
        #pragma unroll
        for (int nt = 0; nt < 4; nt++) {
            int coln = n0 + nw*32 + nt*8 + lm4*2;
            float b0 = bias[coln], b1 = bias[coln+1];
            g_QKV[row0*384 + coln]       = c[mi][nt][0] + b0;
            g_QKV[row0*384 + coln+1]     = c[mi][nt][1] + b1;
            g_QKV[(row0+8)*384 + coln]   = c[mi][nt][2] + b0;
            g_QKV[(row0+8)*384 + coln+1] = c[mi][nt][3] + b1;
        }
    }
}

// ================= K4b: SIMT GEMM for instruction tokens (M=160) =================
__global__ void __launch_bounds__(256) k_gemm(const float* __restrict__ A,
                                              const float* __restrict__ B,
                                              const float* __restrict__ bias,
                                              int M, int N) {
    __shared__ float As[64*68];
    __shared__ float Bs[64*68];
    float* C = g_QKVI;
    int m0 = blockIdx.x*64, n0 = blockIdx.y*64;
    int tid = threadIdx.x, tx = tid & 15, ty = tid >> 4;
    float acc[4][4] = {};
    for (int kc = 0; kc < 2; kc++) {
        int k0 = kc * 64;
        __syncthreads();
        for (int i = tid; i < 1024; i += 256) {
            int row = i >> 4, kq = i & 15;
            float4 v = make_float4(0.f,0.f,0.f,0.f);
            if (m0 + row < M) v = *(const float4*)&A[(size_t)(m0+row)*128 + k0 + kq*4];
            As[(kq*4+0)*68+row]=v.x; As[(kq*4+1)*68+row]=v.y; As[(kq*4+2)*68+row]=v.z; As[(kq*4+3)*68+row]=v.w;
        }
        for (int i = tid; i < 1024; i += 256) {
            int row = i >> 4, kq = i & 15;
            float4 v = *(const float4*)&B[(size_t)(n0+row)*128 + k0 + kq*4];
            Bs[(kq*4+0)*68+row]=v.x; Bs[(kq*4+1)*68+row]=v.y; Bs[(kq*4+2)*68+row]=v.z; Bs[(kq*4+3)*68+row]=v.w;
        }
        __syncthreads();
        #pragma unroll 8
        for (int k = 0; k < 64; k++) {
            float4 aq = *(const float4*)&As[k*68 + ty*4];
            float4 bq = *(const float4*)&Bs[k*68 + tx*4];
            float av[4] = {aq.x, aq.y, aq.z, aq.w};
            float bv[4] = {bq.x, bq.y, bq.z, bq.w};
            #pragma unroll
            for (int i = 0; i < 4; i++)
                #pragma unroll
                for (int j = 0; j < 4; j++)
                    acc[i][j] += av[i]*bv[j];
        }
    }
    #pragma unroll
    for (int i = 0; i < 4; i++) {
        int m = m0 + ty*4 + i;
        if (m < M) {
            #pragma unroll
            for (int j = 0; j < 4; j++) {
                int n = n0 + tx*4 + j;
                C[(size_t)m*N + n] = acc[i][j] + bias[n];
            }
        }
    }
}

// ================= K5: windowed attention with instruction keys =================
__global__ void __launch_bounds__(256) k_attn(const float* __restrict__ bias_c,
                                              const float* __restrict__ bias_i) {
    __shared__ float k_s[NK*36];
    __shared__ float v_s[NK*36];
    int widx = blockIdx.x, head = blockIdx.y, b = blockIdx.z;
    int tid = threadIdx.x;
    int tokbase = (b*NWIN + widx)*TTOK;
    int qoff = head*HD, koff = 128 + head*HD, voff = 256 + head*HD;

    for (int i = tid; i < NI*32; i += 256) {
        int n = i >> 5, ch = i & 31;
        const float* r = &g_QKVI[(size_t)(b*NI + n)*384];
        k_s[n*36 + ch] = r[koff + ch];
        v_s[n*36 + ch] = r[voff + ch];
    }
    for (int i = tid; i < 64*32; i += 256) {
        int t = i >> 5, ch = i & 31;
        const float* r = &g_QKV[(size_t)(tokbase+t)*384];
        k_s[(NI+t)*36 + ch] = r[koff + ch];
        v_s[(NI+t)*36 + ch] = r[voff + ch];
    }
    __syncthreads();

    int qt = tid >> 2, kg = tid & 3;
    const float* qp = &g_QKV[(size_t)(tokbase+qt)*384 + qoff];
    float4 qr[8];
    #pragma unroll
    for (int c = 0; c < 8; c++) qr[c] = *(const float4*)&qp[c*4];

    const float scale = 0.17677669529663687f;
    float p[36];
    float mloc = -1e30f;
    #pragma unroll 4
    for (int j = 0; j < 36; j++) {
        int kt = kg + 4*j;
        float acc = 0.f;
        #pragma unroll
        for (int c = 0; c < 8; c++) {
            float4 kv = *(const float4*)&k_s[kt*36 + c*4];
            acc += qr[c].x*kv.x + qr[c].y*kv.y + qr[c].z*kv.z + qr[c].w*kv.w;
        }
        float bv = (kt < NI) ? bias_i[(head*64 + qt)*NI + kt]
                             : bias_c[(head*64 + qt)*64 + (kt - NI)];
        p[j] = acc*scale + bv;
        mloc = fmaxf(mloc, p[j]);
    }
    mloc = fmaxf(mloc, __shfl_xor_sync(0xffffffffu, mloc, 1));
    mloc = fmaxf(mloc, __shfl_xor_sync(0xffffffffu, mloc, 2));
    float s = 0.f;
    #pragma unroll
    for (int j = 0; j < 36; j++) { p[j] = __expf(p[j] - mloc); s += p[j]; }
    s += __shfl_xor_sync(0xffffffffu, s, 1);
    s += __shfl_xor_sync(0xffffffffu, s, 2);
    float inv = 1.f / s;

    float acc[32];
    #pragma unroll
    for (int c = 0; c < 32; c++) acc[c] = 0.f;
    #pragma unroll 4
    for (int j = 0; j < 36; j++) {
        int kt = kg + 4*j;
        float pj = p[j];
        const float* vb = &v_s[kt*36];
        #pragma unroll
        for (int c = 0; c < 8; c++) {
            float4 v = *(const float4*)&vb[c*4];
            acc[c*4+0] += pj*v.x; acc[c*4+1] += pj*v.y;
            acc[c*4+2] += pj*v.z; acc[c*4+3] += pj*v.w;
        }
    }
    #pragma unroll
    for (int c = 0; c < 32; c++) {
        acc[c] += __shfl_xor_sync(0xffffffffu, acc[c], 1);
        acc[c] += __shfl_xor_sync(0xffffffffu, acc[c], 2);
    }
    float* op = &g_O[(size_t)(tokbase + qt)*COUT + head*HD + kg*8];
    *(float4*)(op    ) = make_float4(acc[kg*8+0]*inv, acc[kg*8+1]*inv, acc[kg*8+2]*inv, acc[kg*8+3]*inv);
    *(float4*)(op + 4) = make_float4(acc[kg*8+4]*inv, acc[kg*8+5]*inv, acc[kg*8+6]*inv, acc[kg*8+7]*inv);
}

// ================= K6: proj + residual + un-window -> output (B,C,H,W,D) =================
__global__ void __launch_bounds__(256) k_proj(const float* __restrict__ pw,
                                              const float* __restrict__ pb,
                                              float* __restrict__ out) {
    __shared__ float pw_s[64*130];
    __shared__ float o_s [128*20];
    int w = blockIdx.x, h = blockIdx.y, b = blockIdx.z;
    int tid = threadIdx.x;
    int nh = h >> 3, wh = h & 7, nw8 = w >> 3, ww = w & 7;
    int wbase = (nh*8 + nw8)*16;
    int ttok  = wh*8 + ww;
    int tok0  = (b*NWIN + wbase)*TTOK + ttok;

    for (int i = tid; i < 2048; i += 256) {
        int d = i >> 7, k = i & 127;
        o_s[k*20 + d] = g_O[(size_t)(tok0 + d*TTOK)*COUT + k];
    }
    int c = tid & 127, dg = tid >> 7;
    float acc[8] = {};
    for (int kc = 0; kc < 2; kc++) {
        __syncthreads();
        for (int i = tid; i < 8192; i += 256) {
            int cc = i >> 6, kk = i & 63;
            pw_s[kk*130 + cc] = pw[(size_t)cc*128 + kc*64 + kk];
        }
        __syncthreads();
        #pragma unroll 8
        for (int k = 0; k < 64; k++) {
            float wv = pw_s[k*130 + c];
            float4 v0 = *(const float4*)&o_s[(kc*64 + k)*20 + dg*8];
            float4 v1 = *(const float4*)&o_s[(kc*64 + k)*20 + dg*8 + 4];
            acc[0]+=wv*v0.x; acc[1]+=wv*v0.y; acc[2]+=wv*v0.z; acc[3]+=wv*v0.w;
            acc[4]+=wv*v1.x; acc[5]+=wv*v1.y; acc[6]+=wv*v1.z; acc[7]+=wv*v1.w;
        }
    }
    float bias = pb[c];
    #pragma unroll
    for (int j = 0; j < 8; j++) {
        int d = dg*8 + j;
        acc[j] += g_RES[(size_t)(tok0 + d*TTOK)*COUT + c] + bias;
    }
    size_t obase = ((size_t)(b*COUT + c))*HWD + h*1024 + w*16;
    *(float4*)&out[obase + dg*8    ] = make_float4(acc[0], acc[1], acc[2], acc[3]);
    *(float4*)&out[obase + dg*8 + 4] = make_float4(acc[4], acc[5], acc[6], acc[7]);
}

// ================= launch =================
extern "C" void kernel_launch(void* const* d_in, const int* in_sizes, int n_in,
                              void* d_out, int out_size) {
    const float* x     = (const float*)d_in[0];
    const float* xsk   = (const float*)d_in[1];
    const float* xins  = (const float*)d_in[2];
    const float* ng    = (const float*)d_in[3];
    const float* nbeta = (const float*)d_in[4];
    const float* cw    = (const float*)d_in[5];
    const float* cb    = (const float*)d_in[6];
    const float* lg    = (const float*)d_in[7];
    const float* lbeta = (const float*)d_in[8];
    const float* qw    = (const float*)d_in[9];
    const float* qb    = (const float*)d_in[10];
    const float* pw    = (const float*)d_in[11];
    const float* pb    = (const float*)d_in[12];
    const float* bc    = (const float*)d_in[13];
    const float* bi    = (const float*)d_in[14];
    float* out = (float*)d_out;

    k_repack   <<<1728, 256>>>(cw);
    k_repack_qw<<<192, 256>>>(qw);
    k_build_xc <<<dim3(HS, CTOT, Bn), 256>>>(x, xsk);
    k_stats    <<<CTOT, 256>>>(ng, nbeta);
    k_conv     <<<dim3(8, HS, Bn), 256>>>(cb, lg, lbeta);
    k_gemm_tc  <<<dim3(NTOK/128, 3), 256>>>(qb);
    k_gemm     <<<dim3(3, 6), 256>>>(xins, qw, qb, Bn*NI, 384);
    k_attn     <<<dim3(NWIN, HEADS, Bn), 256>>>(bc, bi);
    k_proj     <<<dim3(WS, HS, Bn), 256>>>(pw, pb, out);
}